// round 1
// baseline (speedup 1.0000x reference)
#include <cuda_runtime.h>

// Precomputed weight trig (cos, sin), rearranged for conflict-free smem access.
__device__ float2 g_w1[16];    // [co*4 + i*2 + j]
__device__ float2 g_w2[512];   // [(c*16 + i*4 + j)*8 + co]   (co fastest)
__device__ float2 g_wf[2880];  // [o*288 + f]                 (f fastest per output)

__global__ void prep_kernel(const float* __restrict__ w1,
                            const float* __restrict__ w2,
                            const float* __restrict__ wf) {
    int t = threadIdx.x;
    if (t < 16) {
        float s, c; sincosf(w1[t], &s, &c);
        g_w1[t] = make_float2(c, s);
    }
    for (int i = t; i < 512; i += blockDim.x) {
        int co = i >> 6, r = i & 63;          // src: co*64 + (c*16+i*4+j)
        float s, c; sincosf(w2[i], &s, &c);
        g_w2[r * 8 + co] = make_float2(c, s);
    }
    for (int i = t; i < 2880; i += blockDim.x) {
        int f = i / 10, o = i % 10;           // src: f*10 + o
        float s, c; sincosf(wf[i], &s, &c);
        g_wf[o * 288 + f] = make_float2(c, s);
    }
}

__global__ __launch_bounds__(320) void ring_kernel(const float* __restrict__ x,
                                                   float* __restrict__ out) {
    __shared__ float2 s_px[784];   // (cos,sin) of input pixels, 28x28
    __shared__ float2 s_h1[784];   // conv1 out unit vectors, [c*196 + y*14 + x]
    __shared__ float2 s_h2[288];   // conv2 out unit vectors, [ (ho*6+wo)*8 + co ]
    __shared__ float2 s_w1[16];
    __shared__ float2 s_w2[512];
    __shared__ float2 s_wf[2880];

    const int tid = threadIdx.x;
    const int b = blockIdx.x;
    const float* xb = x + b * 784;

    // Stage 0: pixel trig + weight staging
    for (int i = tid; i < 784; i += 320) {
        float s, c; sincosf(xb[i], &s, &c);
        s_px[i] = make_float2(c, s);
    }
    if (tid < 16) s_w1[tid] = g_w1[tid];
    for (int i = tid; i < 512; i += 320) s_w2[i] = g_w2[i];
    for (int i = tid; i < 2880; i += 320) s_wf[i] = g_wf[i];
    __syncthreads();

    // Stage 1: conv1 (2x2, stride 2): 14x14x4 outputs
    for (int idx = tid; idx < 784; idx += 320) {
        int co = idx / 196, p = idx % 196;
        int py = p / 14, px = p % 14;
        int base = (py * 2) * 28 + px * 2;
        float Sx = 0.f, Sy = 0.f;
#pragma unroll
        for (int i = 0; i < 2; i++)
#pragma unroll
            for (int j = 0; j < 2; j++) {
                float2 v = s_px[base + i * 28 + j];
                float2 w = s_w1[co * 4 + i * 2 + j];
                Sx += v.x * w.x + v.y * w.y;   // cos(a-b)
                Sy += v.y * w.x - v.x * w.y;   // sin(a-b)
            }
        float r = rsqrtf(fmaxf(Sx * Sx + Sy * Sy, 1e-30f));
        s_h1[idx] = make_float2(Sx * r, Sy * r);
    }
    __syncthreads();

    // Stage 2: conv2 (4x4, stride 2, 4->8 ch): 6x6x8 = 288 outputs
    if (tid < 288) {
        int co = tid & 7, sp = tid >> 3;      // co fastest -> s_h1 broadcast
        int ho = sp / 6, wo = sp % 6;
        float Sx = 0.f, Sy = 0.f;
#pragma unroll
        for (int c = 0; c < 4; c++)
#pragma unroll
            for (int i = 0; i < 4; i++) {
                int ib = c * 196 + (2 * ho + i) * 14 + 2 * wo;
                int wb = (c * 16 + i * 4) * 8 + co;
#pragma unroll
                for (int j = 0; j < 4; j++) {
                    float2 v = s_h1[ib + j];
                    float2 w = s_w2[wb + j * 8];
                    Sx += v.x * w.x + v.y * w.y;
                    Sy += v.y * w.x - v.x * w.y;
                }
            }
        float r = rsqrtf(fmaxf(Sx * Sx + Sy * Sy, 1e-30f));
        s_h2[tid] = make_float2(Sx * r, Sy * r);
    }
    __syncthreads();

    // Stage 3: FF ring layer, one warp per output class (10 warps)
    int wid = tid >> 5, lane = tid & 31;
    float Sx = 0.f, Sy = 0.f;
#pragma unroll
    for (int f = lane; f < 288; f += 32) {
        float2 v = s_h2[f];
        float2 w = s_wf[wid * 288 + f];
        Sx += v.x * w.x + v.y * w.y;
        Sy += v.y * w.x - v.x * w.y;
    }
#pragma unroll
    for (int off = 16; off; off >>= 1) {
        Sx += __shfl_xor_sync(0xffffffff, Sx, off);
        Sy += __shfl_xor_sync(0xffffffff, Sy, off);
    }
    if (lane == 0)
        out[b * 10 + wid] = Sy * rsqrtf(fmaxf(Sx * Sx + Sy * Sy, 1e-30f));
}

extern "C" void kernel_launch(void* const* d_in, const int* in_sizes, int n_in,
                              void* d_out, int out_size) {
    const float* x  = (const float*)d_in[0];
    const float* w1 = (const float*)d_in[1];
    const float* w2 = (const float*)d_in[2];
    const float* wf = (const float*)d_in[3];
    float* out = (float*)d_out;
    int B = in_sizes[0] / 784;
    prep_kernel<<<1, 512>>>(w1, w2, wf);
    ring_kernel<<<B, 320>>>(x, out);
}

// round 2
// speedup vs baseline: 1.1809x; 1.1809x over previous
#include <cuda_runtime.h>

typedef unsigned long long ull;

// ---- SoA weight planes (cos / sin), device globals filled by prep kernel ----
__device__ float g_w1c[16],   g_w1s[16];     // [co*4 + i*2 + j]
__device__ float g_w2c[544],  g_w2s[544];    // [co*68 + (c*16 + i*4 + j)]  (pad 64->68)
__device__ float g_wfc[2880], g_wfs[2880];   // [o*288 + f]

__global__ void prep_kernel(const float* __restrict__ w1,
                            const float* __restrict__ w2,
                            const float* __restrict__ wf) {
    int t = threadIdx.x;
    if (t < 16) {
        float s, c; __sincosf(w1[t], &s, &c);
        g_w1c[t] = c; g_w1s[t] = s;
    }
    for (int i = t; i < 512; i += blockDim.x) {
        int co = i >> 6, r = i & 63;
        float s, c; __sincosf(w2[i], &s, &c);
        g_w2c[co * 68 + r] = c; g_w2s[co * 68 + r] = s;
    }
    for (int i = t; i < 2880; i += blockDim.x) {
        int f = i / 10, o = i % 10;
        float s, c; __sincosf(wf[i], &s, &c);
        g_wfc[o * 288 + f] = c; g_wfs[o * 288 + f] = s;
    }
}

// packed dual-FMA: acc(lo,hi) += a(lo,hi) * b(lo,hi)
static __device__ __forceinline__ void ffma2(ull& acc, ull a, ull b) {
    asm("fma.rn.f32x2 %0, %1, %2, %0;" : "+l"(acc) : "l"(a), "l"(b));
}
static __device__ __forceinline__ float f2lo(ull v) { return __uint_as_float((unsigned)v); }
static __device__ __forceinline__ float f2hi(ull v) { return __uint_as_float((unsigned)(v >> 32)); }

__global__ __launch_bounds__(320) void ring_kernel(const float* __restrict__ x,
                                                   float* __restrict__ out) {
    __shared__ __align__(16) float s_pxc[784], s_pxs[784];   // input pixel (cos,sin), 28x28
    __shared__ __align__(16) float s_h1c[896], s_h1s[896];   // conv1 out, [c*224 + y*16 + x] (14->16 pad)
    __shared__ __align__(16) float s_h2c[288], s_h2s[288];   // conv2 out, [(ho*6+wo)*8 + co]
    __shared__ __align__(16) float s_w1c[16],  s_w1s[16];
    __shared__ __align__(16) float s_w2c[544], s_w2s[544];

    const int tid = threadIdx.x;
    const float* xb = x + blockIdx.x * 784;

    // ---- Stage 0: pixel trig (SoA) + weight staging ----
    for (int i = tid; i < 784; i += 320) {
        float s, c; __sincosf(xb[i], &s, &c);
        s_pxc[i] = c; s_pxs[i] = s;
    }
    if (tid < 16) { s_w1c[tid] = g_w1c[tid]; s_w1s[tid] = g_w1s[tid]; }
    for (int i = tid; i < 544; i += 320) { s_w2c[i] = g_w2c[i]; s_w2s[i] = g_w2s[i]; }
    __syncthreads();

    // ---- Stage 1: conv1 2x2 s2 -> 14x14x4, packed over j-pairs ----
    for (int idx = tid; idx < 784; idx += 320) {
        int co = idx / 196, p = idx % 196;
        int py = p / 14, px = p % 14;
        int base = py * 56 + px * 2;          // (py*2)*28 + px*2, even
        ull vc0 = *(const ull*)&s_pxc[base];
        ull vs0 = *(const ull*)&s_pxs[base];
        ull vc1 = *(const ull*)&s_pxc[base + 28];
        ull vs1 = *(const ull*)&s_pxs[base + 28];
        ulonglong2 wc = *(const ulonglong2*)&s_w1c[co * 4];
        ulonglong2 ws = *(const ulonglong2*)&s_w1s[co * 4];
        ull T1 = 0, T2 = 0, T3 = 0, T4 = 0;
        ffma2(T1, vc0, wc.x); ffma2(T1, vc1, wc.y);
        ffma2(T2, vs0, ws.x); ffma2(T2, vs1, ws.y);
        ffma2(T3, vs0, wc.x); ffma2(T3, vs1, wc.y);
        ffma2(T4, vc0, ws.x); ffma2(T4, vc1, ws.y);
        float Sx = (f2lo(T1) + f2hi(T1)) + (f2lo(T2) + f2hi(T2));
        float Sy = (f2lo(T3) + f2hi(T3)) - (f2lo(T4) + f2hi(T4));
        float r = rsqrtf(fmaxf(Sx * Sx + Sy * Sy, 1e-30f));
        int dst = co * 224 + py * 16 + px;
        s_h1c[dst] = Sx * r; s_h1s[dst] = Sy * r;
    }
    __syncthreads();

    // ---- Stage 2: conv2 4x4 s2, 4->8 ch -> 288 outputs ----
    if (tid < 288) {
        int co = tid & 7, sp = tid >> 3;       // co fastest -> v broadcast in 8-lane groups
        int ho = sp / 6, wo = sp % 6;
        const int vb0 = ho * 32 + wo * 2;      // (2ho)*16 + 2wo
        const int wb0 = co * 68;
        ull T1 = 0, T2 = 0, T3 = 0, T4 = 0;
#pragma unroll
        for (int c = 0; c < 4; c++) {
#pragma unroll
            for (int i = 0; i < 4; i++) {
                int vb = c * 224 + vb0 + i * 16;
                ull vc01 = *(const ull*)&s_h1c[vb];
                ull vc23 = *(const ull*)&s_h1c[vb + 2];
                ull vs01 = *(const ull*)&s_h1s[vb];
                ull vs23 = *(const ull*)&s_h1s[vb + 2];
                int wb = wb0 + c * 16 + i * 4;          // 16B aligned
                ulonglong2 wc = *(const ulonglong2*)&s_w2c[wb];
                ulonglong2 ws = *(const ulonglong2*)&s_w2s[wb];
                ffma2(T1, vc01, wc.x); ffma2(T1, vc23, wc.y);
                ffma2(T2, vs01, ws.x); ffma2(T2, vs23, ws.y);
                ffma2(T3, vs01, wc.x); ffma2(T3, vs23, wc.y);
                ffma2(T4, vc01, ws.x); ffma2(T4, vc23, ws.y);
            }
        }
        float Sx = (f2lo(T1) + f2hi(T1)) + (f2lo(T2) + f2hi(T2));
        float Sy = (f2lo(T3) + f2hi(T3)) - (f2lo(T4) + f2hi(T4));
        float r = rsqrtf(fmaxf(Sx * Sx + Sy * Sy, 1e-30f));
        s_h2c[tid] = Sx * r; s_h2s[tid] = Sy * r;
    }
    __syncthreads();

    // ---- Stage 3: FF ring layer, one warp per class; wf straight from global ----
    int o = tid >> 5, lane = tid & 31;
    const ull* wfc = reinterpret_cast<const ull*>(g_wfc) + o * 144;
    const ull* wfs = reinterpret_cast<const ull*>(g_wfs) + o * 144;
    ull T1 = 0, T2 = 0, T3 = 0, T4 = 0;
    for (int p = lane; p < 144; p += 32) {     // p indexes f-pairs
        ull vc = *(const ull*)&s_h2c[2 * p];
        ull vs = *(const ull*)&s_h2s[2 * p];
        ull wc = __ldg(wfc + p);
        ull ws = __ldg(wfs + p);
        ffma2(T1, vc, wc); ffma2(T2, vs, ws);
        ffma2(T3, vs, wc); ffma2(T4, vc, ws);
    }
    float Sx = (f2lo(T1) + f2hi(T1)) + (f2lo(T2) + f2hi(T2));
    float Sy = (f2lo(T3) + f2hi(T3)) - (f2lo(T4) + f2hi(T4));
#pragma unroll
    for (int off = 16; off; off >>= 1) {
        Sx += __shfl_xor_sync(0xffffffff, Sx, off);
        Sy += __shfl_xor_sync(0xffffffff, Sy, off);
    }
    if (lane == 0)
        out[blockIdx.x * 10 + o] = Sy * rsqrtf(fmaxf(Sx * Sx + Sy * Sy, 1e-30f));
}

extern "C" void kernel_launch(void* const* d_in, const int* in_sizes, int n_in,
                              void* d_out, int out_size) {
    const float* x  = (const float*)d_in[0];
    const float* w1 = (const float*)d_in[1];
    const float* w2 = (const float*)d_in[2];
    const float* wf = (const float*)d_in[3];
    float* out = (float*)d_out;
    int B = in_sizes[0] / 784;
    prep_kernel<<<1, 512>>>(w1, w2, wf);
    ring_kernel<<<B, 320>>>(x, out);
}